// round 4
// baseline (speedup 1.0000x reference)
#include <cuda_runtime.h>

// out[r,k] = 2^-11 * (WHT_2048(concat(x1,x2))[r,k])^2
// RZ phase is unit-modulus -> cancels under |.|^2; input real -> state real.
//
// Persistent-block, software-pipelined version:
//   - 256 threads own one row (8 elems/thread), block loops over rows with
//     stride gridDim.x; next row's LDG.128s issue before current row's compute.
//   - p1 regs  : bits 0..2  (ownership i = t*8 + e, contiguous LDG.128 x2)
//   - shuffles : bits 3..7  (lane bits, 5 stages, sign-fold FFMA)
//   - transpose: XOR-swizzled smem (double-buffered, 1 sync/row)
//   - p2 regs  : bits 8..10 (ownership i = j*256 + t, coalesced scalar STG)

__global__ __launch_bounds__(256, 8)
void qfl_wht_kernel(const float* __restrict__ x1,
                    const float* __restrict__ x2,
                    float* __restrict__ out, int rows)
{
    __shared__ float smem[2][2048];

    const int t    = threadIdx.x;       // 0..255
    const int lane = t & 31;

    // Per-thread base into the concatenated row (row stride = 1024 floats in
    // whichever source tensor this thread reads from).
    const float* src0 = (t < 128) ? (x1 + (size_t)t * 8)
                                  : (x2 + (size_t)(t - 128) * 8);

    int row = blockIdx.x;
    const int stride = gridDim.x;

    // Prologue: load first row.
    float4 a0, a1;
    {
        const float4* p = (const float4*)(src0 + (size_t)row * 1024);
        a0 = __ldg(p);
        a1 = __ldg(p + 1);
    }

    int buf = 0;
    while (row < rows) {
        float v[8];
        v[0] = a0.x; v[1] = a0.y; v[2] = a0.z; v[3] = a0.w;
        v[4] = a1.x; v[5] = a1.y; v[6] = a1.z; v[7] = a1.w;

        // Prefetch next row — latency overlapped with this row's compute.
        const int nrow = row + stride;
        if (nrow < rows) {
            const float4* p = (const float4*)(src0 + (size_t)nrow * 1024);
            a0 = __ldg(p);
            a1 = __ldg(p + 1);
        }

        // ---- WHT bits 0..2: in-register butterflies (e index) -------------
#pragma unroll
        for (int b = 0; b < 3; ++b) {
            const int m = 1 << b;
#pragma unroll
            for (int j = 0; j < 8; ++j) {
                if ((j & m) == 0) {
                    float a = v[j], c = v[j | m];
                    v[j]     = a + c;
                    v[j | m] = a - c;
                }
            }
        }

        // ---- WHT bits 3..7: shuffle butterflies, sign-fold FFMA -----------
#pragma unroll
        for (int sb = 0; sb < 5; ++sb) {
            const int m = 1 << sb;
            const float sgn = (lane & m) ? -1.0f : 1.0f;
#pragma unroll
            for (int j = 0; j < 8; ++j) {
                float w = __shfl_xor_sync(0xffffffffu, v[j], m);
                v[j] = fmaf(sgn, v[j], w);   // up: w - v ; down: v + w
            }
        }

        // ---- XOR-swizzled smem transpose (double-buffered) ----------------
        float* s = smem[buf];
        {
            float4* s4 = (float4*)s;
            int f0 = 2 * t;
            int f1 = 2 * t + 1;
            s4[f0 ^ ((f0 >> 3) & 7)] = make_float4(v[0], v[1], v[2], v[3]);
            s4[f1 ^ ((f1 >> 3) & 7)] = make_float4(v[4], v[5], v[6], v[7]);
        }
        __syncthreads();

        // ---- Re-own i = j*256 + t; bits 8..10 butterflies; square+store ---
        float u[8];
#pragma unroll
        for (int j = 0; j < 8; ++j) {
            int i  = (j << 8) | t;
            int f  = i >> 2;
            int fs = f ^ ((f >> 3) & 7);
            u[j] = s[fs * 4 + (i & 3)];
        }

#pragma unroll
        for (int b = 0; b < 3; ++b) {
            const int m = 1 << b;
#pragma unroll
            for (int j = 0; j < 8; ++j) {
                if ((j & m) == 0) {
                    float a = u[j], c = u[j | m];
                    u[j]     = a + c;
                    u[j | m] = a - c;
                }
            }
        }

        const float scale = 1.0f / 2048.0f;
        float* orow = out + (size_t)row * 2048 + t;
#pragma unroll
        for (int j = 0; j < 8; ++j) {
            orow[(size_t)(j << 8)] = u[j] * u[j] * scale;
        }

        buf ^= 1;
        row = nrow;
    }
}

extern "C" void kernel_launch(void* const* d_in, const int* in_sizes, int n_in,
                              void* d_out, int out_size)
{
    const float* x1 = (const float*)d_in[0];   // (8192, 1024) f32
    const float* x2 = (const float*)d_in[1];   // (8192, 1024) f32
    float* out = (float*)d_out;                // (8192, 2048) f32

    const int rows = in_sizes[0] / 1024;       // 8192
    int grid = 148 * 8;                        // persistent: ~7 rows/block
    if (grid > rows) grid = rows;
    qfl_wht_kernel<<<grid, 256>>>(x1, x2, out, rows);
}

// round 5
// speedup vs baseline: 1.2272x; 1.2272x over previous
#include <cuda_runtime.h>

// out[r,k] = 2^-11 * (WHT_2048(concat(x1,x2))[r,k])^2
// RZ phase cancels under |.|^2; real input -> real state.
//
// Shuffle-free factorization, 128 threads/row, 16 elems/thread:
//   phase1 regs: bits 7..10  (i = r*128 + t, 16 coalesced scalar LDG)
//   phase2 regs: bits 2..5   (after transpose 1; in-place write-back)
//   phase3 regs: bits 0,1,6  (LDS.128 reads, STG.128 coalesced stores)
// Padded smem layout a(i) = i[10:7]*136 + i[6]*68 + i[5:0]  -> every smem
// access pattern (STS1, LDS1, STS2, LDS2.128) is bank-conflict-free.

__global__ __launch_bounds__(256, 8)
void qfl_wht_kernel(const float* __restrict__ x1,
                    const float* __restrict__ x2,
                    float* __restrict__ out)
{
    __shared__ float smem[2][2176];      // 2 rows per block, 8704B each

    const int t   = threadIdx.x & 127;   // thread within row
    const int sub = threadIdx.x >> 7;    // which row of the pair
    const int row = (blockIdx.x << 1) | sub;
    float* s = smem[sub];

    // ---- Phase 1 load: i = r*128 + t (bits 7..10 in regs), coalesced ------
    float v[16];
    const float* p1 = x1 + (size_t)row * 1024 + t;
    const float* p2 = x2 + (size_t)row * 1024 + t;
#pragma unroll
    for (int r = 0; r < 8; ++r) v[r]     = __ldg(p1 + (r << 7));
#pragma unroll
    for (int r = 0; r < 8; ++r) v[8 + r] = __ldg(p2 + (r << 7));

    // butterflies on bits 7..10 (r index)
#pragma unroll
    for (int m = 1; m <= 8; m <<= 1) {
#pragma unroll
        for (int r = 0; r < 16; ++r) {
            if (!(r & m)) {
                float a = v[r], b = v[r | m];
                v[r]     = a + b;
                v[r | m] = a - b;
            }
        }
    }

    // ---- Transpose 1: a(i) = r*136 + i6*68 + i[5:0]; i[6:0] = t ----------
    {
        const int wbase = ((t >> 6) * 68) + (t & 63);
#pragma unroll
        for (int r = 0; r < 16; ++r) s[r * 136 + wbase] = v[r];
    }
    __syncthreads();

    // ---- Phase 2: regs own q = i[5:2]; t holds i[10:7]=t>>3, i6=t[2], i[1:0]=t[1:0]
    const int base2 = (t >> 3) * 136 + ((t >> 2) & 1) * 68 + (t & 3);
#pragma unroll
    for (int q = 0; q < 16; ++q) v[q] = s[base2 + (q << 2)];

    // butterflies on bits 2..5 (q index)
#pragma unroll
    for (int m = 1; m <= 8; m <<= 1) {
#pragma unroll
        for (int q = 0; q < 16; ++q) {
            if (!(q & m)) {
                float a = v[q], b = v[q | m];
                v[q]     = a + b;
                v[q | m] = a - b;
            }
        }
    }

    // in-place write-back (same ownership partition -> race-free)
#pragma unroll
    for (int q = 0; q < 16; ++q) s[base2 + (q << 2)] = v[q];
    __syncthreads();

    // ---- Phase 3: regs own i[1:0] (in float4), i6 (d&1), i7 (d>>1) --------
    const int base3 = (t >> 4) * 272 + ((t & 15) << 2);
    float4 u[4];
#pragma unroll
    for (int d = 0; d < 4; ++d) {
        const int off = (d >> 1) * 136 + (d & 1) * 68;
        u[d] = *(const float4*)&s[base3 + off];   // conflict-free LDS.128
    }

    // butterflies on bits 0 and 1 (inside float4)
#pragma unroll
    for (int d = 0; d < 4; ++d) {
        float a0 = u[d].x, a1 = u[d].y, a2 = u[d].z, a3 = u[d].w;
        float s0 = a0 + a1, d0 = a0 - a1;
        float s2 = a2 + a3, d2v = a2 - a3;
        u[d].x = s0 + s2;  u[d].z = s0 - s2;
        u[d].y = d0 + d2v; u[d].w = d0 - d2v;
    }
    // butterfly on bit 6 (d&1): pairs (0,1) and (2,3)
#pragma unroll
    for (int dd = 0; dd < 4; dd += 2) {
        float4 a = u[dd], b = u[dd + 1];
        u[dd]     = make_float4(a.x + b.x, a.y + b.y, a.z + b.z, a.w + b.w);
        u[dd + 1] = make_float4(a.x - b.x, a.y - b.y, a.z - b.z, a.w - b.w);
    }

    // ---- Square, scale, fully-coalesced STG.128 ---------------------------
    const float sc = 1.0f / 2048.0f;
    float* o = out + (size_t)row * 2048 + (t >> 4) * 256 + ((t & 15) << 2);
#pragma unroll
    for (int d = 0; d < 4; ++d) {
        float4 w = u[d];
        w.x = w.x * w.x * sc;
        w.y = w.y * w.y * sc;
        w.z = w.z * w.z * sc;
        w.w = w.w * w.w * sc;
        *(float4*)&o[(d >> 1) * 128 + (d & 1) * 64] = w;
    }
}

extern "C" void kernel_launch(void* const* d_in, const int* in_sizes, int n_in,
                              void* d_out, int out_size)
{
    const float* x1 = (const float*)d_in[0];   // (8192, 1024) f32
    const float* x2 = (const float*)d_in[1];   // (8192, 1024) f32
    float* out = (float*)d_out;                // (8192, 2048) f32

    const int rows = in_sizes[0] / 1024;       // 8192
    qfl_wht_kernel<<<rows / 2, 256>>>(x1, x2, out);
}

// round 6
// speedup vs baseline: 1.3249x; 1.0796x over previous
#include <cuda_runtime.h>

// out[r,k] = 2^-11 * (WHT_2048(concat(x1,x2))[r,k])^2
// RZ phase cancels under |.|^2; real input -> real state.
//
// One row per 128-thread block (16 blocks/SM, fine-grained waves):
//   phase1 regs: bits 7..10  (i = r*128 + t, 16 coalesced scalar LDG)
//   phase2 regs: bits 2..5   (after transpose 1; in-place write-back)
//   phase3 regs: bits 0,1,6  (+bit7 passenger; LDS.128, coalesced STG.128)
// Padded smem layout a(i) = i[10:7]*136 + i[6]*68 + i[5:0] -> STS1, LDS1,
// STS2, LDS2.128 all bank-conflict-free (verified in R4).

__global__ __launch_bounds__(128, 16)
void qfl_wht_kernel(const float* __restrict__ x1,
                    const float* __restrict__ x2,
                    float* __restrict__ out)
{
    __shared__ float s[2176];            // 8704 B/row

    const int t   = threadIdx.x;         // 0..127
    const int row = blockIdx.x;

    // ---- Phase 1 load: i = r*128 + t (bits 7..10 in regs), coalesced ------
    float v[16];
    const float* p1 = x1 + (size_t)row * 1024 + t;
    const float* p2 = x2 + (size_t)row * 1024 + t;
#pragma unroll
    for (int r = 0; r < 8; ++r) v[r]     = __ldcs(p1 + (r << 7));
#pragma unroll
    for (int r = 0; r < 8; ++r) v[8 + r] = __ldcs(p2 + (r << 7));

    // butterflies on bits 7..10 (r index)
#pragma unroll
    for (int m = 1; m <= 8; m <<= 1) {
#pragma unroll
        for (int r = 0; r < 16; ++r) {
            if (!(r & m)) {
                float a = v[r], b = v[r | m];
                v[r]     = a + b;
                v[r | m] = a - b;
            }
        }
    }

    // ---- Transpose 1: a(i) = i[10:7]*136 + i[6]*68 + i[5:0]; i[6:0] = t ---
    {
        const int wbase = ((t >> 6) * 68) + (t & 63);
#pragma unroll
        for (int r = 0; r < 16; ++r) s[r * 136 + wbase] = v[r];
    }
    __syncthreads();

    // ---- Phase 2: regs own q = i[5:2]; thread: i[10:7]=t>>3, i6=t[2], i[1:0]=t[1:0]
    const int base2 = (t >> 3) * 136 + ((t >> 2) & 1) * 68 + (t & 3);
#pragma unroll
    for (int q = 0; q < 16; ++q) v[q] = s[base2 + (q << 2)];

    // butterflies on bits 2..5 (q index)
#pragma unroll
    for (int m = 1; m <= 8; m <<= 1) {
#pragma unroll
        for (int q = 0; q < 16; ++q) {
            if (!(q & m)) {
                float a = v[q], b = v[q | m];
                v[q]     = a + b;
                v[q | m] = a - b;
            }
        }
    }

    // in-place write-back (identical ownership partition -> race-free)
#pragma unroll
    for (int q = 0; q < 16; ++q) s[base2 + (q << 2)] = v[q];
    __syncthreads();

    // ---- Phase 3: regs own i[1:0] (float4), i6 (d&1), i7 passenger (d>>1) -
    const int base3 = (t >> 4) * 272 + ((t & 15) << 2);
    float4 u[4];
#pragma unroll
    for (int d = 0; d < 4; ++d) {
        const int off = (d >> 1) * 136 + (d & 1) * 68;
        u[d] = *(const float4*)&s[base3 + off];   // conflict-free LDS.128
    }

    // butterflies on bits 0 and 1 (inside float4)
#pragma unroll
    for (int d = 0; d < 4; ++d) {
        float a0 = u[d].x, a1 = u[d].y, a2 = u[d].z, a3 = u[d].w;
        float s0 = a0 + a1, d0 = a0 - a1;
        float s2 = a2 + a3, d2v = a2 - a3;
        u[d].x = s0 + s2;  u[d].z = s0 - s2;
        u[d].y = d0 + d2v; u[d].w = d0 - d2v;
    }
    // butterfly on bit 6 (d&1): pairs (0,1) and (2,3)
#pragma unroll
    for (int dd = 0; dd < 4; dd += 2) {
        float4 a = u[dd], b = u[dd + 1];
        u[dd]     = make_float4(a.x + b.x, a.y + b.y, a.z + b.z, a.w + b.w);
        u[dd + 1] = make_float4(a.x - b.x, a.y - b.y, a.z - b.z, a.w - b.w);
    }

    // ---- Square, scale, fully-coalesced streaming STG.128 -----------------
    const float sc = 1.0f / 2048.0f;
    float* o = out + (size_t)row * 2048 + (t >> 4) * 256 + ((t & 15) << 2);
#pragma unroll
    for (int d = 0; d < 4; ++d) {
        float4 w = u[d];
        w.x = w.x * w.x * sc;
        w.y = w.y * w.y * sc;
        w.z = w.z * w.z * sc;
        w.w = w.w * w.w * sc;
        __stcs((float4*)&o[(d >> 1) * 128 + (d & 1) * 64], w);
    }
}

extern "C" void kernel_launch(void* const* d_in, const int* in_sizes, int n_in,
                              void* d_out, int out_size)
{
    const float* x1 = (const float*)d_in[0];   // (8192, 1024) f32
    const float* x2 = (const float*)d_in[1];   // (8192, 1024) f32
    float* out = (float*)d_out;                // (8192, 2048) f32

    const int rows = in_sizes[0] / 1024;       // 8192
    qfl_wht_kernel<<<rows, 128>>>(x1, x2, out);
}